// round 9
// baseline (speedup 1.0000x reference)
#include <cuda_runtime.h>
#include <cstdint>

// Problem constants (fixed by the dataset)
#define NN 50000
#define DH 128
#define EE 800000
#define KK 256

// ---------------------------------------------------------------------------
// Scratch device globals. Referenced ONLY from device code (host-shadow bug!).
// A-side operands and weights stored k-PAIR-PERMUTED (see permk) so LDS.64
// yields the (k, k+4) mma fragment pair. Weights n-major: g_WB[mode][n][k].
// ---------------------------------------------------------------------------
__device__ uint32_t g_x32 [NN * DH];
__device__ uint32_t g_h32 [NN * DH];
__device__ uint32_t g_rh32[NN * DH];
__device__ uint32_t g_WB  [4 * KK * DH];
__device__ float g_z  [NN * DH];
__device__ float g_y  [NN * DH];
__device__ float g_w  [NN * DH];
// CSR for gather
__device__ int g_deg[NN];
__device__ int g_cur[NN];
__device__ int g_off[NN];
__device__ int g_csr[EE];

__device__ __forceinline__ float sigmoidf_(float v) {
    return 1.0f / (1.0f + __expf(-v));
}
__device__ __forceinline__ uint32_t f2tf32(float f) {
    uint32_t r;
    asm("cvt.rna.tf32.f32 %0, %1;" : "=r"(r) : "f"(f));
    return r;
}
__device__ __forceinline__ int permk(int k) {
    return (k & ~15) | (k & 8) | ((k & 3) << 1) | ((k >> 2) & 1);
}
__device__ __forceinline__ void cpasync16(uint32_t dst, const void* src, int sz) {
    asm volatile("cp.async.ca.shared.global [%0], [%1], 16, %2;"
                 :: "r"(dst), "l"(src), "r"(sz));
}
__device__ __forceinline__ void mma_tf32(float c[4], uint32_t a0, uint32_t a1,
                                         uint32_t a2, uint32_t a3,
                                         uint32_t b0, uint32_t b1) {
    asm volatile(
        "mma.sync.aligned.m16n8k8.row.col.f32.tf32.tf32.f32 "
        "{%0,%1,%2,%3}, {%4,%5,%6,%7}, {%8,%9}, {%0,%1,%2,%3};"
        : "+f"(c[0]), "+f"(c[1]), "+f"(c[2]), "+f"(c[3])
        : "r"(a0), "r"(a1), "r"(a2), "r"(a3), "r"(b0), "r"(b1));
}

// ---------------------------------------------------------------------------
// Prep W: transpose to [mode][n][k_perm] tf32 via smem tile.
// ---------------------------------------------------------------------------
__global__ void prep_w(
    const float* __restrict__ W_xr, const float* __restrict__ W_hr,
    const float* __restrict__ W_xz, const float* __restrict__ W_hz,
    const float* __restrict__ W_l,  const float* __restrict__ W_r)
{
    __shared__ float s[32][33];
    const int kb = blockIdx.x, nb = blockIdx.y, mode = blockIdx.z;
    const int tx = threadIdx.x, ty = threadIdx.y;

#pragma unroll
    for (int r = 0; r < 4; r++) {
        const int k = kb * 32 + ty + r * 8;
        const int n = nb * 32 + tx;
        float v;
        if (mode == 0)      v = (k < 128) ? W_xr[k * DH + n] : W_hr[(k - 128) * DH + n];
        else if (mode == 1) v = (k < 128) ? W_xz[k * DH + n] : W_hz[(k - 128) * DH + n];
        else if (mode == 2) v = W_l[k * DH + n];
        else                v = W_r[k * DH + n];
        s[ty + r * 8][tx] = v;
    }
    __syncthreads();
#pragma unroll
    for (int r = 0; r < 4; r++) {
        const int n = nb * 32 + ty + r * 8;
        const int k = kb * 32 + tx;
        g_WB[(size_t)mode * KK * DH + n * KK + permk(k)] = f2tf32(s[tx][ty + r * 8]);
    }
}

// Prep: tf32(x), tf32(h) with k-pair permutation.
__global__ __launch_bounds__(256) void prep_xh(
    const float* __restrict__ x, const float* __restrict__ h)
{
    const int i = blockIdx.x * blockDim.x + threadIdx.x;  // over NN*DH/4
    if (i >= NN * (DH / 4)) return;
    const int node = i >> 5;
    const int k    = (i & 31) * 4;
    const size_t base = (size_t)node * DH;
    const float4 xv = *(const float4*)&x[(size_t)i * 4];
    const float4 hv = *(const float4*)&h[(size_t)i * 4];
    g_x32[base + permk(k + 0)] = f2tf32(xv.x);
    g_x32[base + permk(k + 1)] = f2tf32(xv.y);
    g_x32[base + permk(k + 2)] = f2tf32(xv.z);
    g_x32[base + permk(k + 3)] = f2tf32(xv.w);
    g_h32[base + permk(k + 0)] = f2tf32(hv.x);
    g_h32[base + permk(k + 1)] = f2tf32(hv.y);
    g_h32[base + permk(k + 2)] = f2tf32(hv.z);
    g_h32[base + permk(k + 3)] = f2tf32(hv.w);
}

// ---------------------------------------------------------------------------
// CSR build: zero -> histogram -> single-block scan -> bucket fill
// ---------------------------------------------------------------------------
__global__ __launch_bounds__(256) void zero_dc()
{
    const int i = blockIdx.x * blockDim.x + threadIdx.x;
    if (i < NN) { g_deg[i] = 0; g_cur[i] = 0; }
}
__global__ __launch_bounds__(256) void hist_kernel(const int* __restrict__ ei)
{
    const int i = blockIdx.x * blockDim.x + threadIdx.x;
    if (i < EE) atomicAdd(&g_deg[ei[EE + i]], 1);
}
__global__ __launch_bounds__(1024) void scan_kernel()
{
    __shared__ int part[1024];
    const int t = threadIdx.x;
    const int CH = (NN + 1023) / 1024;   // 49
    const int base = t * CH;
    int s = 0;
    for (int i = 0; i < CH; i++) {
        const int idx = base + i;
        if (idx < NN) s += g_deg[idx];
    }
    part[t] = s;
    __syncthreads();
    for (int d = 1; d < 1024; d <<= 1) {
        int v = (t >= d) ? part[t - d] : 0;
        __syncthreads();
        part[t] += v;
        __syncthreads();
    }
    int run = (t == 0) ? 0 : part[t - 1];
    for (int i = 0; i < CH; i++) {
        const int idx = base + i;
        if (idx < NN) { g_off[idx] = run; run += g_deg[idx]; }
    }
}
__global__ __launch_bounds__(256) void fill_kernel(const int* __restrict__ ei)
{
    const int i = blockIdx.x * blockDim.x + threadIdx.x;
    if (i >= EE) return;
    const int dst = ei[EE + i];
    const int pos = atomicAdd(&g_cur[dst], 1);
    g_csr[g_off[dst] + pos] = ei[i];
}

// ---------------------------------------------------------------------------
// TF32 tensor-core GEMM, schedule-split version.
// PHASE 1, grid (391, 4):
//   y=0: [x|h] @ WB[0], K=[0,256)  -> rh = sigmoid(c+b_xr)*h (tf32, permk)
//   y=1: [x|h] @ WB[1], K=[0,256)  -> z  = sigmoid(c+b_xz)
//   y=2:  x    @ WB[2], K=[0,128)  -> g_y  (partial: x @ W_l_top)
//   y=3:  x    @ WB[3], K=[0,128)  -> g_w  (partial: x @ W_r_top)
// PHASE 2, grid (391, 2):
//   y=0:  rh   @ WB[2], K=[128,256) -> g_y += (rh @ W_l_bot)
//   y=1:  rh   @ WB[3], K=[128,256) -> g_w += (rh @ W_r_bot)
// Mainloop = round-5/6 proven indexing (BM=128 BN=128 BK=16, 8 warps 64x32,
// 3-stage cp.async, one sync per chunk).
// ---------------------------------------------------------------------------
#define AP 24
#define BP 20
#define ST 3

template <int PHASE>
__global__ __launch_bounds__(256, 2) void gemm2(
    const float* __restrict__ bias_r, const float* __restrict__ bias_z,
    const float* __restrict__ hprev, int Nrows)
{
    __shared__ uint32_t As[ST][128 * AP];
    __shared__ uint32_t Bs[ST][128 * BP];

    const int ymode = blockIdx.y;
    const int wsel  = (PHASE == 1) ? ymode : (2 + ymode);
    const int CH0   = (PHASE == 1) ? 0 : 8;
    const int CH1   = (PHASE == 1) ? ((ymode < 2) ? 16 : 8) : 16;

    const uint32_t* B = g_WB + (size_t)wsel * (KK * DH);

    const int tid  = threadIdx.x;
    const int lane = tid & 31;
    const int wid  = tid >> 5;
    const int row0 = blockIdx.x * 128;
    const int wm   = (wid >> 2) * 64;
    const int wn   = (wid & 3) * 32;
    const int g    = lane >> 2;
    const int t    = lane & 3;

    float acc[4][4][4];
#pragma unroll
    for (int mi = 0; mi < 4; mi++)
#pragma unroll
        for (int ni = 0; ni < 4; ni++)
#pragma unroll
            for (int q = 0; q < 4; q++) acc[mi][ni][q] = 0.0f;

    // stage K-chunk c into buffer buf
    auto stage = [&](int c, int buf) {
        const int k0 = c * 16;
        const uint32_t* Asrc;
        if (PHASE == 2)          Asrc = g_rh32;
        else if (ymode >= 2)     Asrc = g_x32;
        else                     Asrc = (k0 < 128) ? g_x32 : g_h32;
        const int ka = k0 & 127;
#pragma unroll
        for (int i = 0; i < 2; i++) {
            const int id  = tid + i * 256;
            const int row = id >> 2;
            const int kq  = (id & 3) * 4;
            const uint32_t dst = (uint32_t)__cvta_generic_to_shared(
                &As[buf][row * AP + kq]);
            const int sz = (row0 + row < Nrows) ? 16 : 0;
            cpasync16(dst, &Asrc[(size_t)(row0 + row) * DH + ka + kq], sz);
        }
#pragma unroll
        for (int i = 0; i < 2; i++) {
            const int id = tid + i * 256;
            const int n  = id >> 2;
            const int kq = (id & 3) * 4;
            const uint32_t dst = (uint32_t)__cvta_generic_to_shared(
                &Bs[buf][n * BP + kq]);
            cpasync16(dst, &B[(size_t)n * KK + k0 + kq], 16);
        }
        asm volatile("cp.async.commit_group;");
    };

    stage(CH0, 0);
    stage(CH0 + 1, 1);

#pragma unroll 1
    for (int c = CH0; c < CH1; c++) {
        if (c < CH1 - 1) { asm volatile("cp.async.wait_group 1;"); }
        else             { asm volatile("cp.async.wait_group 0;"); }
        __syncthreads();   // all reads of buffer (c+2)%ST's previous contents done

        if (c + 2 < CH1) stage(c + 2, (c - CH0 + 2) % ST);

        const int buf = (c - CH0) % ST;
#pragma unroll
        for (int k8 = 0; k8 < 2; k8++) {
            uint32_t a[4][4], b[4][2];
#pragma unroll
            for (int mi = 0; mi < 4; mi++) {
                const int rb = wm + mi * 16 + g;
                const uint2 lo = *(const uint2*)&As[buf][rb * AP + k8 * 8 + 2 * t];
                const uint2 hi = *(const uint2*)&As[buf][(rb + 8) * AP + k8 * 8 + 2 * t];
                a[mi][0] = lo.x; a[mi][1] = hi.x; a[mi][2] = lo.y; a[mi][3] = hi.y;
            }
#pragma unroll
            for (int ni = 0; ni < 4; ni++) {
                const int cb = wn + ni * 8 + g;
                const uint2 v = *(const uint2*)&Bs[buf][cb * BP + k8 * 8 + 2 * t];
                b[ni][0] = v.x; b[ni][1] = v.y;
            }
#pragma unroll
            for (int mi = 0; mi < 4; mi++)
#pragma unroll
                for (int ni = 0; ni < 4; ni++)
                    mma_tf32(acc[mi][ni], a[mi][0], a[mi][1], a[mi][2], a[mi][3],
                             b[ni][0], b[ni][1]);
        }
    }

    // epilogue: thread owns (row = wm+mi*16+g(+8), cols = wn+ni*8+2t, +1)
#pragma unroll
    for (int mi = 0; mi < 4; mi++) {
#pragma unroll
        for (int half = 0; half < 2; half++) {
            const int grow = row0 + wm + mi * 16 + g + half * 8;
            if (grow >= Nrows) continue;
#pragma unroll
            for (int ni = 0; ni < 4; ni++) {
                const int col = wn + ni * 8 + 2 * t;
                float c0 = acc[mi][ni][half * 2 + 0];
                float c1 = acc[mi][ni][half * 2 + 1];
                const size_t off = (size_t)grow * DH + col;
                if (PHASE == 1) {
                    if (ymode == 0) {
                        c0 = sigmoidf_(c0 + bias_r[col]);
                        c1 = sigmoidf_(c1 + bias_r[col + 1]);
                        const float2 hh = *(const float2*)&hprev[off];
                        const size_t rbase = (size_t)grow * DH;
                        g_rh32[rbase + permk(col)]     = f2tf32(c0 * hh.x);
                        g_rh32[rbase + permk(col + 1)] = f2tf32(c1 * hh.y);
                    } else if (ymode == 1) {
                        float2 o;
                        o.x = sigmoidf_(c0 + bias_z[col]);
                        o.y = sigmoidf_(c1 + bias_z[col + 1]);
                        *(float2*)&g_z[off] = o;
                    } else if (ymode == 2) {
                        *(float2*)&g_y[off] = make_float2(c0, c1);
                    } else {
                        *(float2*)&g_w[off] = make_float2(c0, c1);
                    }
                } else {
                    float* dsta = (ymode == 0) ? g_y : g_w;
                    const float2 prev = *(const float2*)&dsta[off];
                    *(float2*)&dsta[off] = make_float2(prev.x + c0, prev.y + c1);
                }
            }
        }
    }
}

// ---------------------------------------------------------------------------
// Gather + final fused: one warp per node.
// out = (1-z) * (sum_nbr(y)/max(deg,1) + b_l + w) + z * h_prev
// ---------------------------------------------------------------------------
__global__ __launch_bounds__(256) void gather_final(
    const float* __restrict__ hprev, const float* __restrict__ b_l,
    float* __restrict__ out)
{
    const int node = (blockIdx.x * blockDim.x + threadIdx.x) >> 5;
    const int lane = threadIdx.x & 31;
    if (node >= NN) return;

    const int off = g_off[node];
    const int deg = g_deg[node];

    float4 acc = make_float4(0.f, 0.f, 0.f, 0.f);
    int e = 0;
    for (; e + 4 <= deg; e += 4) {
        const int s0 = g_csr[off + e + 0];
        const int s1 = g_csr[off + e + 1];
        const int s2 = g_csr[off + e + 2];
        const int s3 = g_csr[off + e + 3];
        const float4 v0 = *(const float4*)&g_y[(size_t)s0 * DH + lane * 4];
        const float4 v1 = *(const float4*)&g_y[(size_t)s1 * DH + lane * 4];
        const float4 v2 = *(const float4*)&g_y[(size_t)s2 * DH + lane * 4];
        const float4 v3 = *(const float4*)&g_y[(size_t)s3 * DH + lane * 4];
        acc.x += (v0.x + v1.x) + (v2.x + v3.x);
        acc.y += (v0.y + v1.y) + (v2.y + v3.y);
        acc.z += (v0.z + v1.z) + (v2.z + v3.z);
        acc.w += (v0.w + v1.w) + (v2.w + v3.w);
    }
    for (; e < deg; e++) {
        const int s0 = g_csr[off + e];
        const float4 v0 = *(const float4*)&g_y[(size_t)s0 * DH + lane * 4];
        acc.x += v0.x; acc.y += v0.y; acc.z += v0.z; acc.w += v0.w;
    }

    const float inv = 1.0f / (float)max(deg, 1);
    const size_t o = (size_t)node * DH + lane * 4;
    const float4 w  = *(const float4*)&g_w[o];
    const float4 z  = *(const float4*)&g_z[o];
    const float4 hh = *(const float4*)&hprev[o];
    const float4 bl = *(const float4*)&b_l[lane * 4];

    float4 r;
    float n;
    n = fmaf(acc.x, inv, bl.x) + w.x; r.x = (1.0f - z.x) * n + z.x * hh.x;
    n = fmaf(acc.y, inv, bl.y) + w.y; r.y = (1.0f - z.y) * n + z.y * hh.y;
    n = fmaf(acc.z, inv, bl.z) + w.z; r.z = (1.0f - z.z) * n + z.z * hh.z;
    n = fmaf(acc.w, inv, bl.w) + w.w; r.w = (1.0f - z.w) * n + z.w * hh.w;
    *(float4*)&out[o] = r;
}

// ---------------------------------------------------------------------------
extern "C" void kernel_launch(void* const* d_in, const int* in_sizes, int n_in,
                              void* d_out, int out_size)
{
    const float* x    = (const float*)d_in[0];
    const int*   ei   = (const int*)  d_in[1];
    const float* h    = (const float*)d_in[2];
    const float* W_xr = (const float*)d_in[3];
    const float* b_xr = (const float*)d_in[4];
    const float* W_hr = (const float*)d_in[5];
    const float* W_xz = (const float*)d_in[6];
    const float* b_xz = (const float*)d_in[7];
    const float* W_hz = (const float*)d_in[8];
    const float* W_l  = (const float*)d_in[9];
    const float* b_l  = (const float*)d_in[10];
    const float* W_r  = (const float*)d_in[11];
    float* out = (float*)d_out;

    const int gemm_grid = (NN + 127) / 128;   // 391

    // One-time resources (created on the first, non-captured, call)
    static cudaStream_t sC = nullptr;
    static cudaEvent_t evRoot, evC;
    if (!sC) {
        cudaStreamCreateWithFlags(&sC, cudaStreamNonBlocking);
        cudaEventCreateWithFlags(&evRoot, cudaEventDisableTiming);
        cudaEventCreateWithFlags(&evC,    cudaEventDisableTiming);
    }

    // Fork: CSR build hidden on side stream
    cudaEventRecord(evRoot, 0);
    cudaStreamWaitEvent(sC, evRoot, 0);
    zero_dc<<<(NN + 255) / 256, 256, 0, sC>>>();
    hist_kernel<<<(EE + 255) / 256, 256, 0, sC>>>(ei);
    scan_kernel<<<1, 1024, 0, sC>>>();
    fill_kernel<<<(EE + 255) / 256, 256, 0, sC>>>(ei);
    cudaEventRecord(evC, sC);

    // Main stream
    prep_w<<<dim3(8, 4, 4), dim3(32, 8)>>>(W_xr, W_hr, W_xz, W_hz, W_l, W_r);
    prep_xh<<<(NN * (DH / 4) + 255) / 256, 256>>>(x, h);

    // Phase 1: gates (r, z) + x-part of candidate (y_top, w_top) — all independent
    gemm2<1><<<dim3(gemm_grid, 4), 256>>>(b_xr, b_xz, h, NN);
    // Phase 2: rh-part of candidate, accumulate into y/w
    gemm2<2><<<dim3(gemm_grid, 2), 256>>>(b_xr, b_xz, h, NN);

    // Join CSR, then fused gather + final
    cudaStreamWaitEvent(0, evC, 0);
    gather_final<<<(NN * 32 + 255) / 256, 256>>>(h, b_l, out);
}

// round 10
// speedup vs baseline: 1.1077x; 1.1077x over previous
#include <cuda_runtime.h>
#include <cuda_bf16.h>
#include <cstdint>

// Problem constants (fixed by the dataset)
#define NN 50000
#define DH 128
#define EE 800000
#define KK 256

// ---------------------------------------------------------------------------
// Scratch device globals. Referenced ONLY from device code (host-shadow bug!).
// A-side operands and weights stored k-PAIR-PERMUTED (see permk) so LDS.64
// yields the (k, k+4) mma fragment pair. Weights n-major: g_WB[mode][n][k].
// g_ybf: y = xc@W_l stored bf16 (halves gather traffic; precision budgeted).
// ---------------------------------------------------------------------------
__device__ uint32_t g_x32 [NN * DH];
__device__ uint32_t g_h32 [NN * DH];
__device__ uint32_t g_rh32[NN * DH];
__device__ uint32_t g_WB  [4 * KK * DH];
__device__ float g_z  [NN * DH];
__device__ __nv_bfloat16 g_ybf[NN * DH];
__device__ float g_w  [NN * DH];
// CSR for gather
__device__ int g_deg[NN];
__device__ int g_cur[NN];
__device__ int g_off[NN];
__device__ int g_csr[EE];

__device__ __forceinline__ float sigmoidf_(float v) {
    return 1.0f / (1.0f + __expf(-v));
}
__device__ __forceinline__ uint32_t f2tf32(float f) {
    uint32_t r;
    asm("cvt.rna.tf32.f32 %0, %1;" : "=r"(r) : "f"(f));
    return r;
}
__device__ __forceinline__ int permk(int k) {
    return (k & ~15) | (k & 8) | ((k & 3) << 1) | ((k >> 2) & 1);
}
__device__ __forceinline__ void cpasync16(uint32_t dst, const void* src, int sz) {
    asm volatile("cp.async.ca.shared.global [%0], [%1], 16, %2;"
                 :: "r"(dst), "l"(src), "r"(sz));
}
__device__ __forceinline__ void mma_tf32(float c[4], uint32_t a0, uint32_t a1,
                                         uint32_t a2, uint32_t a3,
                                         uint32_t b0, uint32_t b1) {
    asm volatile(
        "mma.sync.aligned.m16n8k8.row.col.f32.tf32.tf32.f32 "
        "{%0,%1,%2,%3}, {%4,%5,%6,%7}, {%8,%9}, {%0,%1,%2,%3};"
        : "+f"(c[0]), "+f"(c[1]), "+f"(c[2]), "+f"(c[3])
        : "r"(a0), "r"(a1), "r"(a2), "r"(a3), "r"(b0), "r"(b1));
}

// ---------------------------------------------------------------------------
// Prep W: transpose to [mode][n][k_perm] tf32 via smem tile.
// ---------------------------------------------------------------------------
__global__ void prep_w(
    const float* __restrict__ W_xr, const float* __restrict__ W_hr,
    const float* __restrict__ W_xz, const float* __restrict__ W_hz,
    const float* __restrict__ W_l,  const float* __restrict__ W_r)
{
    __shared__ float s[32][33];
    const int kb = blockIdx.x, nb = blockIdx.y, mode = blockIdx.z;
    const int tx = threadIdx.x, ty = threadIdx.y;

#pragma unroll
    for (int r = 0; r < 4; r++) {
        const int k = kb * 32 + ty + r * 8;
        const int n = nb * 32 + tx;
        float v;
        if (mode == 0)      v = (k < 128) ? W_xr[k * DH + n] : W_hr[(k - 128) * DH + n];
        else if (mode == 1) v = (k < 128) ? W_xz[k * DH + n] : W_hz[(k - 128) * DH + n];
        else if (mode == 2) v = W_l[k * DH + n];
        else                v = W_r[k * DH + n];
        s[ty + r * 8][tx] = v;
    }
    __syncthreads();
#pragma unroll
    for (int r = 0; r < 4; r++) {
        const int n = nb * 32 + ty + r * 8;
        const int k = kb * 32 + tx;
        g_WB[(size_t)mode * KK * DH + n * KK + permk(k)] = f2tf32(s[tx][ty + r * 8]);
    }
}

// Prep: tf32(x), tf32(h) with k-pair permutation.
__global__ __launch_bounds__(256) void prep_xh(
    const float* __restrict__ x, const float* __restrict__ h)
{
    const int i = blockIdx.x * blockDim.x + threadIdx.x;  // over NN*DH/4
    if (i >= NN * (DH / 4)) return;
    const int node = i >> 5;
    const int k    = (i & 31) * 4;
    const size_t base = (size_t)node * DH;
    const float4 xv = *(const float4*)&x[(size_t)i * 4];
    const float4 hv = *(const float4*)&h[(size_t)i * 4];
    g_x32[base + permk(k + 0)] = f2tf32(xv.x);
    g_x32[base + permk(k + 1)] = f2tf32(xv.y);
    g_x32[base + permk(k + 2)] = f2tf32(xv.z);
    g_x32[base + permk(k + 3)] = f2tf32(xv.w);
    g_h32[base + permk(k + 0)] = f2tf32(hv.x);
    g_h32[base + permk(k + 1)] = f2tf32(hv.y);
    g_h32[base + permk(k + 2)] = f2tf32(hv.z);
    g_h32[base + permk(k + 3)] = f2tf32(hv.w);
}

// ---------------------------------------------------------------------------
// CSR build: zero -> histogram -> single-block scan -> bucket fill
// ---------------------------------------------------------------------------
__global__ __launch_bounds__(256) void zero_dc()
{
    const int i = blockIdx.x * blockDim.x + threadIdx.x;
    if (i < NN) { g_deg[i] = 0; g_cur[i] = 0; }
}
__global__ __launch_bounds__(256) void hist_kernel(const int* __restrict__ ei)
{
    const int i = blockIdx.x * blockDim.x + threadIdx.x;
    if (i < EE) atomicAdd(&g_deg[ei[EE + i]], 1);
}
__global__ __launch_bounds__(1024) void scan_kernel()
{
    __shared__ int part[1024];
    const int t = threadIdx.x;
    const int CH = (NN + 1023) / 1024;   // 49
    const int base = t * CH;
    int s = 0;
    for (int i = 0; i < CH; i++) {
        const int idx = base + i;
        if (idx < NN) s += g_deg[idx];
    }
    part[t] = s;
    __syncthreads();
    for (int d = 1; d < 1024; d <<= 1) {
        int v = (t >= d) ? part[t - d] : 0;
        __syncthreads();
        part[t] += v;
        __syncthreads();
    }
    int run = (t == 0) ? 0 : part[t - 1];
    for (int i = 0; i < CH; i++) {
        const int idx = base + i;
        if (idx < NN) { g_off[idx] = run; run += g_deg[idx]; }
    }
}
__global__ __launch_bounds__(256) void fill_kernel(const int* __restrict__ ei)
{
    const int i = blockIdx.x * blockDim.x + threadIdx.x;
    if (i >= EE) return;
    const int dst = ei[EE + i];
    const int pos = atomicAdd(&g_cur[dst], 1);
    g_csr[g_off[dst] + pos] = ei[i];
}

// ---------------------------------------------------------------------------
// TF32 tensor-core GEMM (round-6 mainloop, round-8 schedule — proven).
//   MODE 0: [x|h]  @ WB0 -> rh (tf32, permk)
//   MODE 1: [x|h]  @ WB1 -> z
//   MODE 2: [x|rh] @ WB2 -> y (bf16!)
//   MODE 3: [x|rh] @ WB3 -> w
// ---------------------------------------------------------------------------
#define AP 24
#define BP 20
#define ST 3

template <int MODE>
__global__ __launch_bounds__(256, 2) void gemm_tf32(
    const float* __restrict__ bias, const float* __restrict__ hprev, int Nrows)
{
    __shared__ uint32_t As[ST][128 * AP];
    __shared__ uint32_t Bs[ST][128 * BP];

    const uint32_t* A0 = g_x32;
    const uint32_t* A1 = (MODE >= 2) ? g_rh32 : g_h32;
    const uint32_t* B  = g_WB + (size_t)MODE * (KK * DH);

    const int tid  = threadIdx.x;
    const int lane = tid & 31;
    const int wid  = tid >> 5;
    const int row0 = blockIdx.x * 128;
    const int wm   = (wid >> 2) * 64;
    const int wn   = (wid & 3) * 32;
    const int g    = lane >> 2;
    const int t    = lane & 3;

    float acc[4][4][4];
#pragma unroll
    for (int mi = 0; mi < 4; mi++)
#pragma unroll
        for (int ni = 0; ni < 4; ni++)
#pragma unroll
            for (int q = 0; q < 4; q++) acc[mi][ni][q] = 0.0f;

    auto stage = [&](int c, int buf) {
        const int k0 = c * 16;
        const uint32_t* Asrc = (k0 < 128) ? A0 : A1;
        const int ka = k0 & 127;
#pragma unroll
        for (int i = 0; i < 2; i++) {
            const int id  = tid + i * 256;
            const int row = id >> 2;
            const int kq  = (id & 3) * 4;
            const uint32_t dst = (uint32_t)__cvta_generic_to_shared(
                &As[buf][row * AP + kq]);
            const int sz = (row0 + row < Nrows) ? 16 : 0;
            cpasync16(dst, &Asrc[(size_t)(row0 + row) * DH + ka + kq], sz);
        }
#pragma unroll
        for (int i = 0; i < 2; i++) {
            const int id = tid + i * 256;
            const int n  = id >> 2;
            const int kq = (id & 3) * 4;
            const uint32_t dst = (uint32_t)__cvta_generic_to_shared(
                &Bs[buf][n * BP + kq]);
            cpasync16(dst, &B[(size_t)n * KK + k0 + kq], 16);
        }
        asm volatile("cp.async.commit_group;");
    };

    uint32_t fa0[4][4], fb0[4][2], fa1[4][4], fb1[4][2];

    auto ldA = [&](uint32_t (&a)[4][4], int buf, int k8) {
#pragma unroll
        for (int mi = 0; mi < 4; mi++) {
            const int rb = wm + mi * 16 + g;
            const uint2 lo = *(const uint2*)&As[buf][rb * AP + k8 * 8 + 2 * t];
            const uint2 hi = *(const uint2*)&As[buf][(rb + 8) * AP + k8 * 8 + 2 * t];
            a[mi][0] = lo.x; a[mi][1] = hi.x; a[mi][2] = lo.y; a[mi][3] = hi.y;
        }
    };
    auto ldB = [&](uint32_t (&b)[4][2], int buf, int k8) {
#pragma unroll
        for (int ni = 0; ni < 4; ni++) {
            const int cb = wn + ni * 8 + g;
            const uint2 v = *(const uint2*)&Bs[buf][cb * BP + k8 * 8 + 2 * t];
            b[ni][0] = v.x; b[ni][1] = v.y;
        }
    };
    auto domma = [&](uint32_t (&a)[4][4], uint32_t (&b)[4][2]) {
#pragma unroll
        for (int mi = 0; mi < 4; mi++)
#pragma unroll
            for (int ni = 0; ni < 4; ni++)
                mma_tf32(acc[mi][ni], a[mi][0], a[mi][1], a[mi][2], a[mi][3],
                         b[ni][0], b[ni][1]);
    };

    stage(0, 0);
    stage(1, 1);
    asm volatile("cp.async.wait_group 1;");
    __syncthreads();
    ldA(fa0, 0, 0); ldB(fb0, 0, 0);

#pragma unroll
    for (int c = 0; c < 16; c++) {
        const int buf = c % ST;
        if (c + 2 < 16) stage(c + 2, (c + 2) % ST);
        ldA(fa1, buf, 1); ldB(fb1, buf, 1);
        domma(fa0, fb0);
        if (c < 15) {
            if (c < 14) { asm volatile("cp.async.wait_group 1;"); }
            else        { asm volatile("cp.async.wait_group 0;"); }
            __syncthreads();
            ldA(fa0, (c + 1) % ST, 0); ldB(fb0, (c + 1) % ST, 0);
        }
        domma(fa1, fb1);
    }

#pragma unroll
    for (int mi = 0; mi < 4; mi++) {
#pragma unroll
        for (int half = 0; half < 2; half++) {
            const int grow = row0 + wm + mi * 16 + g + half * 8;
            if (grow >= Nrows) continue;
#pragma unroll
            for (int ni = 0; ni < 4; ni++) {
                const int col = wn + ni * 8 + 2 * t;
                float c0 = acc[mi][ni][half * 2 + 0];
                float c1 = acc[mi][ni][half * 2 + 1];
                const size_t off = (size_t)grow * DH + col;
                if (MODE == 0) {
                    c0 = sigmoidf_(c0 + bias[col]);
                    c1 = sigmoidf_(c1 + bias[col + 1]);
                    const float2 hh = *(const float2*)&hprev[off];
                    const size_t rbase = (size_t)grow * DH;
                    g_rh32[rbase + permk(col)]     = f2tf32(c0 * hh.x);
                    g_rh32[rbase + permk(col + 1)] = f2tf32(c1 * hh.y);
                } else if (MODE == 1) {
                    float2 o;
                    o.x = sigmoidf_(c0 + bias[col]);
                    o.y = sigmoidf_(c1 + bias[col + 1]);
                    *(float2*)&g_z[off] = o;
                } else if (MODE == 2) {
                    __nv_bfloat162 p;
                    p.x = __float2bfloat16_rn(c0);
                    p.y = __float2bfloat16_rn(c1);
                    *(__nv_bfloat162*)&g_ybf[off] = p;
                } else {
                    *(float2*)&g_w[off] = make_float2(c0, c1);
                }
            }
        }
    }
}

// ---------------------------------------------------------------------------
// Gather + final fused: one warp per node; y rows are bf16 (8B per lane).
// out = (1-z) * (sum_nbr(y)/max(deg,1) + b_l + w) + z * h_prev
// ---------------------------------------------------------------------------
__global__ __launch_bounds__(256) void gather_final(
    const float* __restrict__ hprev, const float* __restrict__ b_l,
    float* __restrict__ out)
{
    const int node = (blockIdx.x * blockDim.x + threadIdx.x) >> 5;
    const int lane = threadIdx.x & 31;
    if (node >= NN) return;

    const int off = g_off[node];
    const int deg = g_deg[node];

    float4 acc = make_float4(0.f, 0.f, 0.f, 0.f);

    auto addrow = [&](int s) {
        const uint2 v = *(const uint2*)&g_ybf[(size_t)s * DH + lane * 4];
        const float2 p0 = __bfloat1622float2(*(const __nv_bfloat162*)&v.x);
        const float2 p1 = __bfloat1622float2(*(const __nv_bfloat162*)&v.y);
        acc.x += p0.x; acc.y += p0.y; acc.z += p1.x; acc.w += p1.y;
    };

    int e = 0;
    for (; e + 4 <= deg; e += 4) {
        const int s0 = g_csr[off + e + 0];
        const int s1 = g_csr[off + e + 1];
        const int s2 = g_csr[off + e + 2];
        const int s3 = g_csr[off + e + 3];
        addrow(s0); addrow(s1); addrow(s2); addrow(s3);
    }
    for (; e < deg; e++) addrow(g_csr[off + e]);

    const float inv = 1.0f / (float)max(deg, 1);
    const size_t o = (size_t)node * DH + lane * 4;
    const float4 w  = *(const float4*)&g_w[o];
    const float4 z  = *(const float4*)&g_z[o];
    const float4 hh = *(const float4*)&hprev[o];
    const float4 bl = *(const float4*)&b_l[lane * 4];

    float4 r;
    float n;
    n = fmaf(acc.x, inv, bl.x) + w.x; r.x = (1.0f - z.x) * n + z.x * hh.x;
    n = fmaf(acc.y, inv, bl.y) + w.y; r.y = (1.0f - z.y) * n + z.y * hh.y;
    n = fmaf(acc.z, inv, bl.z) + w.z; r.z = (1.0f - z.z) * n + z.z * hh.z;
    n = fmaf(acc.w, inv, bl.w) + w.w; r.w = (1.0f - z.w) * n + z.w * hh.w;
    *(float4*)&out[o] = r;
}

// ---------------------------------------------------------------------------
extern "C" void kernel_launch(void* const* d_in, const int* in_sizes, int n_in,
                              void* d_out, int out_size)
{
    const float* x    = (const float*)d_in[0];
    const int*   ei   = (const int*)  d_in[1];
    const float* h    = (const float*)d_in[2];
    const float* W_xr = (const float*)d_in[3];
    const float* b_xr = (const float*)d_in[4];
    const float* W_hr = (const float*)d_in[5];
    const float* W_xz = (const float*)d_in[6];
    const float* b_xz = (const float*)d_in[7];
    const float* W_hz = (const float*)d_in[8];
    const float* W_l  = (const float*)d_in[9];
    const float* b_l  = (const float*)d_in[10];
    const float* W_r  = (const float*)d_in[11];
    float* out = (float*)d_out;

    const int gemm_grid = (NN + 127) / 128;   // 391

    // One-time resources (created on the first, non-captured, call)
    static cudaStream_t sB = nullptr, sC = nullptr;
    static cudaEvent_t evRoot, evA, evG0, evB3, evC;
    if (!sB) {
        cudaStreamCreateWithFlags(&sB, cudaStreamNonBlocking);
        cudaStreamCreateWithFlags(&sC, cudaStreamNonBlocking);
        cudaEventCreateWithFlags(&evRoot, cudaEventDisableTiming);
        cudaEventCreateWithFlags(&evA,    cudaEventDisableTiming);
        cudaEventCreateWithFlags(&evG0,   cudaEventDisableTiming);
        cudaEventCreateWithFlags(&evB3,   cudaEventDisableTiming);
        cudaEventCreateWithFlags(&evC,    cudaEventDisableTiming);
    }

    // Fork point
    cudaEventRecord(evRoot, 0);

    // --- Stream C: CSR build (independent of GEMMs) ---
    cudaStreamWaitEvent(sC, evRoot, 0);
    zero_dc<<<(NN + 255) / 256, 256, 0, sC>>>();
    hist_kernel<<<(EE + 255) / 256, 256, 0, sC>>>(ei);
    scan_kernel<<<1, 1024, 0, sC>>>();
    fill_kernel<<<(EE + 255) / 256, 256, 0, sC>>>(ei);
    cudaEventRecord(evC, sC);

    // --- Main stream: preps ---
    prep_w<<<dim3(8, 4, 4), dim3(32, 8)>>>(W_xr, W_hr, W_xz, W_hz, W_l, W_r);
    prep_xh<<<(NN * (DH / 4) + 255) / 256, 256>>>(x, h);
    cudaEventRecord(evA, 0);

    // --- Stream B: z-gate GEMM (independent of r-gate chain) ---
    cudaStreamWaitEvent(sB, evA, 0);
    gemm_tf32<1><<<gemm_grid, 256, 0, sB>>>(b_xz, h, NN);

    // --- Main stream: r-gate, then y ---
    gemm_tf32<0><<<gemm_grid, 256>>>(b_xr, h, NN);
    cudaEventRecord(evG0, 0);

    // --- Stream B: w (needs rh from g0) ---
    cudaStreamWaitEvent(sB, evG0, 0);
    gemm_tf32<3><<<gemm_grid, 256, 0, sB>>>(nullptr, h, NN);
    cudaEventRecord(evB3, sB);

    gemm_tf32<2><<<gemm_grid, 256>>>(nullptr, h, NN);

    // --- Join: gather+final needs y (main), z & w (sB), CSR (sC) ---
    cudaStreamWaitEvent(0, evB3, 0);
    cudaStreamWaitEvent(0, evC, 0);
    gather_final<<<(NN * 32 + 255) / 256, 256>>>(h, b_l, out);
}